// round 16
// baseline (speedup 1.0000x reference)
#include <cuda_runtime.h>
#include <cuda_fp16.h>
#include <math.h>

#define TT 1024
#define NENV 8192
#define CHUNKS 32
#define STEPS 32            // TT / CHUNKS
#define MTOT (TT * NENV)    // 8388608
#define BLK 256
#define GX (NENV / BLK)     // 32 env columns
#define ENTY 8              // ent-reduction y-slices
// y-slice layout: [0,32) coeff | [32,40) ent | 40 scan | [41,73) main
#define Y_ENT   CHUNKS
#define Y_SCAN  (CHUNKS + ENTY)
#define Y_MAIN  (CHUNKS + ENTY + 1)
#define Y_TOTAL (CHUNKS + ENTY + 1 + CHUNKS)

#define GAMMA_F 0.99f
#define GLF (0.99f * 0.95f)

// ---------------- scratch (device globals; zero-initialized) ------------------
__device__ unsigned g_bu[MTOT];              // packed half2: (b, u) per element
__device__ unsigned g_abits[CHUNKS * NENV];  // per-step a!=0 bit
__device__ float    g_Ag[CHUNKS * NENV];     // chunk aggregate A
__device__ float    g_Bg[CHUNKS * NENV];     // chunk aggregate B
__device__ float    g_SA [CHUNKS * NENV];
__device__ float    g_SB [CHUNKS * NENV];
__device__ float    g_SA2[CHUNKS * NENV];
__device__ float    g_SAB[CHUNKS * NENV];
__device__ float    g_SB2[CHUNKS * NENV];
__device__ float    g_gin[CHUNKS * NENV];    // incoming gae per chunk
__device__ double   g_acc[5];                // 0:Σg 1:Σg² 2:vloss 3:ent 4:action
__device__ float    g_stats[2];              // mean, inv_std
__device__ unsigned g_colcnt[GX];            // coeff blocks done per env column
__device__ unsigned g_entdone;               // ent blocks done
__device__ unsigned g_ready;                 // stats published flag
__device__ unsigned g_tick1, g_tick2;        // tickets (self-reset)

// ---------------- acquire/release helpers ------------------------------------
__device__ __forceinline__ void red_release_add(unsigned* p, unsigned v) {
    asm volatile("red.release.gpu.global.add.u32 [%0], %1;" :: "l"(p), "r"(v) : "memory");
}
__device__ __forceinline__ void st_release(unsigned* p, unsigned v) {
    asm volatile("st.release.gpu.global.u32 [%0], %1;" :: "l"(p), "r"(v) : "memory");
}
__device__ __forceinline__ unsigned ld_acquire(const unsigned* p) {
    unsigned v;
    asm volatile("ld.acquire.gpu.global.u32 %0, [%1];" : "=r"(v) : "l"(p) : "memory");
    return v;
}

// ---------------- block reduce (256 threads = 8 warps) ------------------------
__device__ __forceinline__ float block_reduce(float v, float* smem) {
    #pragma unroll
    for (int o = 16; o > 0; o >>= 1) v += __shfl_down_sync(0xffffffffu, v, o);
    int lane = threadIdx.x & 31, w = threadIdx.x >> 5;
    if (lane == 0) smem[w] = v;
    __syncthreads();
    if (w == 0) {
        v = (lane < 8) ? smem[lane] : 0.0f;
        #pragma unroll
        for (int o = 4; o > 0; o >>= 1) v += __shfl_down_sync(0xffffffffu, v, o);
    }
    return v; // valid on thread 0
}

// ---- the one kernel ----------------------------------------------------------
__global__ void __launch_bounds__(BLK) k_all(
    const float* __restrict__ rew, const float* __restrict__ masks,
    const float* __restrict__ bad, const float* __restrict__ vp,
    const float* __restrict__ lastv, const float* __restrict__ nval,
    const float* __restrict__ ent, const float* __restrict__ lp,
    const float* __restrict__ plp, float* __restrict__ out)
{
    __shared__ float sm0[8], sm1[8];
    const int ybl = blockIdx.y;

    if (ybl < Y_ENT) {
        // ================= coeff path (byte-identical to r8/r13) =============
        const int n  = blockIdx.x * BLK + threadIdx.x;
        const int c  = ybl;
        const int lo = c * STEPS, hi = lo + STEPS;

        float v_next = (hi == TT) ? lastv[n] : vp[hi * NENV + n];
        float A = 1.0f, B = 0.0f;
        float SA = 0.f, SB = 0.f, SA2 = 0.f, SAB = 0.f, SB2 = 0.f;
        unsigned bits = 0u;

        #pragma unroll 8
        for (int t = hi - 1; t >= lo; --t) {
            int idx = t * NENV + n;
            float v  = vp[idx];
            float m  = masks[idx + NENV];
            float bd = bad[idx + NENV];
            float r  = rew[idx];
            float nv = nval[idx];
            float delta = r + GAMMA_F * v_next * m - v;
            float b = delta * bd;
            float u = nv - v;
            __half2 h = __floats2half2_rn(b, u);
            g_bu[idx] = *reinterpret_cast<unsigned*>(&h);
            float br = __half2float(__low2half(h));
            float anz = m * bd;
            bits |= (anz != 0.0f ? 1u : 0u) << (t - lo);
            float a = anz * GLF;
            B = a * B + br;
            A = a * A;
            SA += A;  SB += B;
            SA2 += A * A;  SAB += A * B;  SB2 += B * B;
            v_next = v;
        }
        int ci = c * NENV + n;
        g_abits[ci] = bits;
        g_Ag[ci] = A;   g_Bg[ci] = B;
        g_SA[ci] = SA;  g_SB[ci] = SB;
        g_SA2[ci] = SA2; g_SAB[ci] = SAB; g_SB2[ci] = SB2;

        __syncthreads();
        if (threadIdx.x == 0) red_release_add(&g_colcnt[blockIdx.x], 1u);
        return;
    }

    if (ybl < Y_SCAN) {
        // ================= ent path ==========================================
        const int bid = (ybl - Y_ENT) * GX + blockIdx.x;
        const int nvec = MTOT / 4;
        const int stride = GX * ENTY * BLK;
        const float4* e4 = reinterpret_cast<const float4*>(ent);
        float s = 0.0f;
        for (int i = bid * BLK + threadIdx.x; i < nvec; i += stride) {
            float4 v = e4[i];
            s += (v.x + v.y) + (v.z + v.w);
        }
        float rs = block_reduce(s, sm0);
        if (threadIdx.x == 0) {
            atomicAdd(&g_acc[3], (double)rs);
            red_release_add(&g_entdone, 1u);
        }
        return;
    }

    if (ybl == Y_SCAN) {
        // ================= scan path (per-column gated) ======================
        if (threadIdx.x == 0) {
            while (ld_acquire(&g_colcnt[blockIdx.x]) < CHUNKS) __nanosleep(128);
        }
        __syncthreads();

        const int n = blockIdx.x * BLK + threadIdx.x;
        float g = 0.0f, sg = 0.0f, sg2 = 0.0f;
        #pragma unroll
        for (int c = CHUNKS - 1; c >= 0; --c) {
            int i = c * NENV + n;
            g_gin[i] = g;
            sg  += g_SA[i] * g + g_SB[i];
            sg2 += (g_SA2[i] * g + 2.0f * g_SAB[i]) * g + g_SB2[i];
            g = g_Ag[i] * g + g_Bg[i];
        }

        float rs  = block_reduce(sg,  sm0);
        float rs2 = block_reduce(sg2, sm1);
        if (threadIdx.x == 0) {
            g_colcnt[blockIdx.x] = 0u;          // self-reset (all 32 arrived)
            atomicAdd(&g_acc[0], (double)rs);
            atomicAdd(&g_acc[1], (double)rs2);
            __threadfence();
            unsigned t = atomicAdd(&g_tick1, 1u);
            if (t == GX - 1) {
                volatile double* acc = g_acc;
                double S = acc[0], S2 = acc[1];
                double M = (double)MTOT;
                double mean = S / M;
                double var = (S2 - S * S / M) / (M - 1.0);
                g_stats[0] = (float)mean;
                g_stats[1] = (float)(1.0 / (sqrt(var) + 1e-5));
                g_acc[0] = 0.0; g_acc[1] = 0.0;
                g_tick1 = 0u;
                st_release(&g_ready, 1u);       // publish stats
            }
        }
        return;
    }

    // ================= main path (byte-identical body to r9) =================
    if (threadIdx.x == 0) {
        while (ld_acquire(&g_ready) == 0u) __nanosleep(128);
    }
    __syncthreads();

    const int n  = blockIdx.x * BLK + threadIdx.x;
    const int c  = ybl - Y_MAIN;
    const int lo = c * STEPS, hi = lo + STEPS;
    const int ci = c * NENV + n;

    const float mean = g_stats[0], istd = g_stats[1];
    float g = g_gin[ci];
    const unsigned bits = g_abits[ci];

    float vl = 0.f, act = 0.f;
    #pragma unroll 8
    for (int t = hi - 1; t >= lo; --t) {
        const int idx = t * NENV + n;
        unsigned buw = g_bu[idx];
        __half2 h = *reinterpret_cast<const __half2*>(&buw);
        float2 bu = __half22float2(h);
        float am = ((bits >> (t - lo)) & 1u) ? GLF : 0.0f;
        g = fmaf(am, g, bu.x);

        float a = (g - mean) * istd;
        float r = __expf(lp[idx] - plp[idx]);
        float rc = fminf(fmaxf(r, 0.8f), 1.2f);
        act += fminf(r * a, rc * a);

        float u  = bu.y;
        float d1 = u - g;
        float d2 = fminf(fmaxf(u, -0.2f), 0.2f) - g;
        vl += fmaxf(d1 * d1, d2 * d2);
    }

    float rvl = block_reduce(vl,  sm0);
    float rac = block_reduce(act, sm1);
    if (threadIdx.x == 0) {
        atomicAdd(&g_acc[2], (double)rvl);
        atomicAdd(&g_acc[4], (double)rac);
        __threadfence();
        unsigned tk = atomicAdd(&g_tick2, 1u);
        if (tk == GX * CHUNKS - 1) {
            // gate on ent completion (ent blocks finished long ago in practice)
            while (ld_acquire(&g_entdone) < (unsigned)(GX * ENTY)) __nanosleep(128);
            volatile double* acc = g_acc;
            double M = (double)MTOT;
            double value_term = 0.25 * (acc[2] / M);
            double action_loss = -(acc[4] / M);
            double ent_mean = acc[3] / M;
            out[0] = (float)(value_term + action_loss - 0.01 * ent_mean);
            g_acc[2] = 0.0; g_acc[3] = 0.0; g_acc[4] = 0.0;  // self-reset
            g_tick2 = 0u;
            g_entdone = 0u;
            g_ready = 0u;
        }
    }
}

// ---------------- launch ------------------------------------------------------
extern "C" void kernel_launch(void* const* d_in, const int* in_sizes, int n_in,
                              void* d_out, int out_size)
{
    const float* rew   = (const float*)d_in[0];
    const float* masks = (const float*)d_in[1];
    const float* bad   = (const float*)d_in[2];
    const float* vp    = (const float*)d_in[3];
    const float* lastv = (const float*)d_in[4];
    const float* lp    = (const float*)d_in[5];
    const float* plp   = (const float*)d_in[6];
    const float* nval  = (const float*)d_in[7];
    const float* ent   = (const float*)d_in[8];
    float* out = (float*)d_out;

    dim3 grid(GX, Y_TOTAL);
    k_all<<<grid, BLK>>>(rew, masks, bad, vp, lastv, nval, ent, lp, plp, out);
}

// round 17
// speedup vs baseline: 1.2051x; 1.2051x over previous
#include <cuda_runtime.h>
#include <cuda_fp16.h>
#include <math.h>

#define TT 1024
#define NENV 8192
#define CHUNKS 32
#define STEPS 32            // TT / CHUNKS
#define MTOT (TT * NENV)    // 8388608
#define BLK 256
#define GX (NENV / BLK)     // 32 env columns
#define ENTY 8              // ent-reduction y-slices
#define EPB 32              // envs per scan block
#define GSCAN (NENV / EPB)  // 256 scan blocks
#define SP 33               // smem pitch (bank-conflict-free transpose)

#define GAMMA_F 0.99f
#define GLF (0.99f * 0.95f)

// ---------------- scratch (device globals; zero-initialized) ------------------
__device__ unsigned g_bu[MTOT];              // packed half2: (b, u) per element
__device__ unsigned g_abits[CHUNKS * NENV];  // per-step a!=0 bit
__device__ float    g_Ag[CHUNKS * NENV];     // chunk aggregate A
__device__ float    g_Bg[CHUNKS * NENV];     // chunk aggregate B
__device__ float    g_SA [CHUNKS * NENV];
__device__ float    g_SB [CHUNKS * NENV];
__device__ float    g_SA2[CHUNKS * NENV];
__device__ float    g_SAB[CHUNKS * NENV];
__device__ float    g_SB2[CHUNKS * NENV];
__device__ float    g_gin[CHUNKS * NENV];    // incoming gae per chunk
__device__ double   g_acc[5];                // 0:Σg 1:Σg² 2:vloss 3:ent 4:action
__device__ float    g_stats[2];              // mean, inv_std
__device__ unsigned g_tick1, g_tick2;        // self-resetting tickets

// ---------------- block reduce (256 threads = 8 warps) ------------------------
__device__ __forceinline__ float block_reduce(float v, float* smem) {
    #pragma unroll
    for (int o = 16; o > 0; o >>= 1) v += __shfl_down_sync(0xffffffffu, v, o);
    int lane = threadIdx.x & 31, w = threadIdx.x >> 5;
    if (lane == 0) smem[w] = v;
    __syncthreads();
    if (w == 0) {
        v = (lane < 8) ? smem[lane] : 0.0f;
        #pragma unroll
        for (int o = 4; o > 0; o >>= 1) v += __shfl_down_sync(0xffffffffu, v, o);
    }
    return v; // valid on thread 0
}

// ---- K1: coeff slices + ent slices (== round 13, the 73.7% DRAM kernel) ------
__global__ void __launch_bounds__(BLK) k_fused(
    const float* __restrict__ rew, const float* __restrict__ masks,
    const float* __restrict__ bad, const float* __restrict__ vp,
    const float* __restrict__ lastv, const float* __restrict__ nval,
    const float* __restrict__ ent)
{
    __shared__ float sm[8];

    if (blockIdx.y >= CHUNKS) {
        // ---------- ent path: independent grid-stride float4 sum ----------
        const int bid = (blockIdx.y - CHUNKS) * GX + blockIdx.x;
        const int nvec = MTOT / 4;
        const int stride = GX * ENTY * BLK;
        const float4* e4 = reinterpret_cast<const float4*>(ent);
        float s = 0.0f;
        for (int i = bid * BLK + threadIdx.x; i < nvec; i += stride) {
            float4 v = e4[i];
            s += (v.x + v.y) + (v.z + v.w);
        }
        float rs = block_reduce(s, sm);
        if (threadIdx.x == 0) atomicAdd(&g_acc[3], (double)rs);
        return;
    }

    // ---------- coeff path: byte-identical to round 8/13 ----------
    const int n  = blockIdx.x * BLK + threadIdx.x;
    const int c  = blockIdx.y;
    const int lo = c * STEPS, hi = lo + STEPS;

    float v_next = (hi == TT) ? lastv[n] : vp[hi * NENV + n];
    float A = 1.0f, B = 0.0f;
    float SA = 0.f, SB = 0.f, SA2 = 0.f, SAB = 0.f, SB2 = 0.f;
    unsigned bits = 0u;

    #pragma unroll 8
    for (int t = hi - 1; t >= lo; --t) {
        int idx = t * NENV + n;
        float v  = vp[idx];
        float m  = masks[idx + NENV];
        float bd = bad[idx + NENV];
        float r  = rew[idx];
        float nv = nval[idx];
        float delta = r + GAMMA_F * v_next * m - v;
        float b = delta * bd;
        float u = nv - v;
        __half2 h = __floats2half2_rn(b, u);
        g_bu[idx] = *reinterpret_cast<unsigned*>(&h);
        float br = __half2float(__low2half(h));  // fp16-rounded b (consistent!)
        float anz = m * bd;                       // exactly 0 or 1
        bits |= (anz != 0.0f ? 1u : 0u) << (t - lo);
        float a = anz * GLF;
        B = a * B + br;
        A = a * A;
        SA += A;  SB += B;
        SA2 += A * A;  SAB += A * B;  SB2 += B * B;
        v_next = v;
    }
    int ci = c * NENV + n;
    g_abits[ci] = bits;
    g_Ag[ci] = A;   g_Bg[ci] = B;
    g_SA[ci] = SA;  g_SB[ci] = SB;
    g_SA2[ci] = SA2; g_SAB[ci] = SAB; g_SB2[ci] = SB2;
}

// ---- K2: warp-parallel affine suffix scan + Σg, Σg² + stats ------------------
__global__ void __launch_bounds__(BLK) k_scan() {
    __shared__ float sA[CHUNKS * SP], sB[CHUNKS * SP];
    __shared__ float s1[CHUNKS * SP], s2[CHUNKS * SP], s3[CHUNKS * SP];
    __shared__ float s4[CHUNKS * SP], s5[CHUNKS * SP];
    __shared__ float sm0[8], sm1[8];

    const int t  = threadIdx.x;
    const int nb = blockIdx.x * EPB;

    // phase 1: coalesced gmem -> smem (tile: 32 chunks x 32 envs)
    #pragma unroll
    for (int k = 0; k < (CHUNKS * EPB) / BLK; ++k) {   // 4 iters
        int i2 = k * BLK + t;
        int c = i2 >> 5, e = i2 & 31;
        int gi = c * NENV + nb + e;
        int si = c * SP + e;
        sA[si] = g_Ag[gi];  sB[si] = g_Bg[gi];
        s1[si] = g_SA[gi];  s2[si] = g_SB[gi];
        s3[si] = g_SA2[gi]; s4[si] = g_SAB[gi]; s5[si] = g_SB2[gi];
    }
    __syncthreads();

    // phase 2: per-env warp suffix scan (lane = chunk); 4 envs per warp
    const int lane = t & 31, w = t >> 5;
    float sg = 0.f, sg2 = 0.f;
    #pragma unroll
    for (int q = 0; q < 4; ++q) {
        const int e  = w * 4 + q;
        const int si = lane * SP + e;
        float A = sA[si], Bv = sB[si];
        // Kogge-Stone suffix composition: G_c = F_c ∘ F_{c+1} ∘ ... ∘ F_31
        #pragma unroll
        for (int d = 1; d < 32; d <<= 1) {
            float A2 = __shfl_down_sync(0xffffffffu, A, d);
            float B2 = __shfl_down_sync(0xffffffffu, Bv, d);
            if (lane + d < 32) { Bv = fmaf(A, B2, Bv); A = A * A2; }
        }
        // g_in(c) = G_{c+1}(0) = B of lane c+1 ; g_in(31) = 0
        float gin = __shfl_down_sync(0xffffffffu, Bv, 1);
        if (lane == 31) gin = 0.0f;

        sg  += fmaf(s1[si], gin, s2[si]);
        sg2 += fmaf(fmaf(s3[si], gin, 2.0f * s4[si]), gin, s5[si]);
        sA[si] = gin;                         // stash for coalesced writeback
    }
    __syncthreads();

    // phase 3: coalesced smem -> gmem for g_gin
    #pragma unroll
    for (int k = 0; k < (CHUNKS * EPB) / BLK; ++k) {
        int i2 = k * BLK + t;
        int c = i2 >> 5, e = i2 & 31;
        g_gin[c * NENV + nb + e] = sA[c * SP + e];
    }

    float rs  = block_reduce(sg,  sm0);
    float rs2 = block_reduce(sg2, sm1);
    if (threadIdx.x == 0) {
        atomicAdd(&g_acc[0], (double)rs);
        atomicAdd(&g_acc[1], (double)rs2);
        __threadfence();
        unsigned tk = atomicAdd(&g_tick1, 1u);
        if (tk == GSCAN - 1) {
            volatile double* acc = g_acc;
            double S = acc[0], S2 = acc[1];
            double M = (double)MTOT;
            double mean = S / M;
            double var = (S2 - S * S / M) / (M - 1.0);
            g_stats[0] = (float)mean;
            g_stats[1] = (float)(1.0 / (sqrt(var) + 1e-5));
            g_acc[0] = 0.0; g_acc[1] = 0.0;     // self-reset for next replay
            g_tick1 = 0u;
        }
    }
}

// ---- K3: fused main pass (reads bu, lp, plp only) (== round 9) ---------------
__global__ void __launch_bounds__(BLK) k_main(
    const float* __restrict__ lp, const float* __restrict__ plp,
    float* __restrict__ out)
{
    __shared__ float sm0[8], sm1[8];
    const int n  = blockIdx.x * BLK + threadIdx.x;
    const int c  = blockIdx.y;
    const int lo = c * STEPS, hi = lo + STEPS;
    const int ci = c * NENV + n;

    const float mean = g_stats[0], istd = g_stats[1];
    float g = g_gin[ci];
    const unsigned bits = g_abits[ci];

    float vl = 0.f, act = 0.f;
    #pragma unroll 8
    for (int t = hi - 1; t >= lo; --t) {
        const int idx = t * NENV + n;
        unsigned buw = g_bu[idx];
        __half2 h = *reinterpret_cast<const __half2*>(&buw);
        float2 bu = __half22float2(h);
        float am = ((bits >> (t - lo)) & 1u) ? GLF : 0.0f;
        g = fmaf(am, g, bu.x);                    // gae recurrence

        float a = (g - mean) * istd;
        float r = __expf(lp[idx] - plp[idx]);
        float rc = fminf(fmaxf(r, 0.8f), 1.2f);
        act += fminf(r * a, rc * a);

        float u  = bu.y;
        float d1 = u - g;
        float d2 = fminf(fmaxf(u, -0.2f), 0.2f) - g;
        vl += fmaxf(d1 * d1, d2 * d2);
    }

    float rvl = block_reduce(vl,  sm0);
    float rac = block_reduce(act, sm1);
    if (threadIdx.x == 0) {
        atomicAdd(&g_acc[2], (double)rvl);
        atomicAdd(&g_acc[4], (double)rac);
        __threadfence();
        unsigned tk = atomicAdd(&g_tick2, 1u);
        if (tk == gridDim.x * gridDim.y - 1) {
            volatile double* acc = g_acc;
            double M = (double)MTOT;
            double value_term = 0.25 * (acc[2] / M);   // 0.5*mean * VALUE_LOSS_COEF
            double action_loss = -(acc[4] / M);
            double ent_mean = acc[3] / M;
            out[0] = (float)(value_term + action_loss - 0.01 * ent_mean);
            g_acc[2] = 0.0; g_acc[3] = 0.0; g_acc[4] = 0.0;  // self-reset
            g_tick2 = 0u;
        }
    }
}

// ---------------- launch ------------------------------------------------------
extern "C" void kernel_launch(void* const* d_in, const int* in_sizes, int n_in,
                              void* d_out, int out_size)
{
    const float* rew   = (const float*)d_in[0];
    const float* masks = (const float*)d_in[1];
    const float* bad   = (const float*)d_in[2];
    const float* vp    = (const float*)d_in[3];
    const float* lastv = (const float*)d_in[4];
    const float* lp    = (const float*)d_in[5];
    const float* plp   = (const float*)d_in[6];
    const float* nval  = (const float*)d_in[7];
    const float* ent   = (const float*)d_in[8];
    float* out = (float*)d_out;

    dim3 gridA(GX, CHUNKS + ENTY);   // coeff(32) + ent(8) slices
    dim3 gridM(GX, CHUNKS);
    k_fused<<<gridA, BLK>>>(rew, masks, bad, vp, lastv, nval, ent);
    k_scan<<<GSCAN, BLK>>>();
    k_main<<<gridM, BLK>>>(lp, plp, out);
}